// round 14
// baseline (speedup 1.0000x reference)
#include <cuda_runtime.h>
#include <cuda_fp16.h>
#include <math.h>
#include <stdint.h>

// ---------------------------------------------------------------------------
#define Bv   2
#define Nv   2048
#define Cv   1024
#define Hv   16
#define Dv   64
#define HIDv 4096
#define Rv   (Bv*Nv)

#define OFF_X1        0LL
#define OFF_HBASE     4194304LL
#define SCRATCH_TOTAL 29360128LL

#define HOFF_XN     0LL
#define HOFF_QKV    4194304LL
#define HOFF_OATT   16777216LL
#define HOFF_HMID   20971520LL
#define HOFF_WQKV   37748736LL
#define HOFF_WPROJ  40894464LL
#define HOFF_WFC1   41943040LL
#define HOFF_WFC2   46137344LL

__device__ float g_scratch[SCRATCH_TOTAL];

// ---------------------------------------------------------------------------
__device__ __forceinline__ float ex2(float x) {
    float y;
    asm("ex2.approx.f32 %0, %1;" : "=f"(y) : "f"(x));
    return y;
}
__device__ __forceinline__ uint32_t smem_u32(const void* p) {
    uint32_t a;
    asm("{ .reg .u64 t; cvta.to.shared.u64 t, %1; cvt.u32.u64 %0, t; }"
        : "=r"(a) : "l"(p));
    return a;
}
__device__ __forceinline__ void cp_async16(void* sm, const void* gm) {
    uint32_t s = smem_u32(sm);
    asm volatile("cp.async.cg.shared.global [%0], [%1], 16;" :: "r"(s), "l"(gm));
}
__device__ __forceinline__ void cp_commit() {
    asm volatile("cp.async.commit_group;");
}
__device__ __forceinline__ void cp_wait0() {
    asm volatile("cp.async.wait_group 0;");
}
__device__ __forceinline__ void cp_wait1() {
    asm volatile("cp.async.wait_group 1;");
}
__device__ __forceinline__ void mma_f16(float* d, const uint32_t* a, const uint32_t* b) {
    asm volatile(
        "mma.sync.aligned.m16n8k16.row.col.f32.f16.f16.f32 "
        "{%0,%1,%2,%3}, {%4,%5,%6,%7}, {%8,%9}, {%0,%1,%2,%3};"
        : "+f"(d[0]), "+f"(d[1]), "+f"(d[2]), "+f"(d[3])
        : "r"(a[0]), "r"(a[1]), "r"(a[2]), "r"(a[3]), "r"(b[0]), "r"(b[1]));
}
__device__ __forceinline__ void ldsm4(uint32_t& r0, uint32_t& r1, uint32_t& r2,
                                      uint32_t& r3, uint32_t a) {
    asm volatile("ldmatrix.sync.aligned.m8n8.x4.shared.b16 {%0,%1,%2,%3}, [%4];"
        : "=r"(r0), "=r"(r1), "=r"(r2), "=r"(r3) : "r"(a));
}
__device__ __forceinline__ void ldsm4t(uint32_t& r0, uint32_t& r1, uint32_t& r2,
                                       uint32_t& r3, uint32_t a) {
    asm volatile("ldmatrix.sync.aligned.m8n8.x4.trans.shared.b16 {%0,%1,%2,%3}, [%4];"
        : "=r"(r0), "=r"(r1), "=r"(r2), "=r"(r3) : "r"(a));
}

// ---------------------------------------------------------------------------
// LayerNorm: fp32 in, fp16 out. 256 threads/row, single float4 pass.
// ---------------------------------------------------------------------------
__global__ void ln_kernel(const float* __restrict__ x,
                          const float* __restrict__ g,
                          const float* __restrict__ b,
                          __half* __restrict__ out)
{
    const int row = blockIdx.x;
    const int tid = threadIdx.x;
    const float4 v = *((const float4*)(x + (size_t)row * Cv) + tid);

    float lsum = v.x + v.y + v.z + v.w;
    float lsq  = v.x * v.x + v.y * v.y + v.z * v.z + v.w * v.w;

    __shared__ float s1[8], s2[8], sm_[2];
    for (int o = 16; o; o >>= 1) {
        lsum += __shfl_down_sync(0xffffffffu, lsum, o);
        lsq  += __shfl_down_sync(0xffffffffu, lsq,  o);
    }
    const int wid = tid >> 5, lid = tid & 31;
    if (!lid) { s1[wid] = lsum; s2[wid] = lsq; }
    __syncthreads();
    if (tid < 8) {
        float a = s1[tid], c = s2[tid];
        for (int o = 4; o; o >>= 1) {
            a += __shfl_down_sync(0xffu, a, o);
            c += __shfl_down_sync(0xffu, c, o);
        }
        if (!tid) {
            const float mean = a * (1.0f / Cv);
            sm_[0] = mean;
            sm_[1] = rsqrtf(c * (1.0f / Cv) - mean * mean + 1e-5f);
        }
    }
    __syncthreads();
    const float mean = sm_[0], rstd = sm_[1];

    const float4 gg = *((const float4*)g + tid);
    const float4 bb = *((const float4*)b + tid);
    half2 o0 = __floats2half2_rn((v.x - mean) * rstd * gg.x + bb.x,
                                 (v.y - mean) * rstd * gg.y + bb.y);
    half2 o1 = __floats2half2_rn((v.z - mean) * rstd * gg.z + bb.z,
                                 (v.w - mean) * rstd * gg.w + bb.w);
    uint2 st = make_uint2(*(uint32_t*)&o0, *(uint32_t*)&o1);
    *((uint2*)(out + (size_t)row * Cv) + tid) = st;
}

// ---------------------------------------------------------------------------
// One streaming fp32 -> fp16 convert over all 4 weight matrices
// ---------------------------------------------------------------------------
__global__ void convert_h(const float* __restrict__ wqkv,  __half* __restrict__ oqkv,
                          const float* __restrict__ wproj, __half* __restrict__ oproj,
                          const float* __restrict__ wfc1,  __half* __restrict__ ofc1,
                          const float* __restrict__ wfc2,  __half* __restrict__ ofc2)
{
    long long i = (long long)blockIdx.x * blockDim.x + threadIdx.x;
    const float* src; __half* dst;
    if (i < 786432)        { src = wqkv;  dst = oqkv; }
    else if (i < 1048576)  { src = wproj; dst = oproj; i -= 786432; }
    else if (i < 2097152)  { src = wfc1;  dst = ofc1;  i -= 1048576; }
    else                   { src = wfc2;  dst = ofc2;  i -= 2097152; }
    float4 v = *(const float4*)(src + i * 4);
    *(half2*)(dst + i * 4)     = __floats2half2_rn(v.x, v.y);
    *(half2*)(dst + i * 4 + 2) = __floats2half2_rn(v.z, v.w);
}

// ---------------------------------------------------------------------------
// Fused flash attention, register-direct P (no P smem), warps 4m x 2n.
// Grid (1,16,32), 256 threads = 8 warps, 2 CTAs/SM.
// Warp (wm,wn): S tile = rows wm*32..+32, cols wn*64..+64; PV accumulates the
// partial over its own 64 k-cols into full 64 O columns (oacc[2][8][4]);
// 2-way cross-wn reduction at the end. K and V double-buffered:
// chunk loop = 1 wait_group(0) + 1 __syncthreads.
// ---------------------------------------------------------------------------
#define QSTR 72
#define KSTR 72
#define VSTR 72
#define NCHUNKS 16

__global__ void __launch_bounds__(256, 2)
fused_attn(const __half* __restrict__ qkv, __half* __restrict__ oatt)
{
    extern __shared__ __half sh[];
    __half* Qs  = sh;                            // 128*72
    __half* Kb0 = sh + 9216;
    __half* Kb1 = sh + 18432;
    __half* Vb0 = sh + 27648;
    __half* Vb1 = sh + 36864;
    float*  red  = (float*)(sh + 46080);         // 256 floats
    float*  linv = red + 256;                    // 128 floats
    float*  fbuf = (float*)sh;                   // epilogue alias: 128 x 66 f32

    const int tid  = threadIdx.x;
    const int lane = tid & 31, warp = tid >> 5;
    const int wm = warp & 3, wn = warp >> 2;     // 4m x 2n
    const int g = lane >> 2, t4 = lane & 3;
    const int l8 = lane & 7, grp = lane >> 3;
    const int lm16 = lane & 15, lh = lane >> 4;

    const uint32_t uQ = smem_u32(Qs);

    const int bh = blockIdx.z;
    const int b = bh >> 4, h = bh & 15;
    const int qbase = b * Nv + blockIdx.y * 128;
    const int kvbase = b * Nv;
    const float LOG2E_SCALE = 0.18033688011112042f;  // 0.125 * log2(e)

    auto loadT = [&](__half* dst, const __half* src) {
        #pragma unroll
        for (int p = 0; p < 4; p++) {
            int idx = tid + p * 256;
            int row = idx >> 3, c8 = (idx & 7) << 3;
            cp_async16(dst + row * QSTR + c8, src + (size_t)row * 3072 + c8);
        }
    };

    float oacc[2][8][4];
    #pragma unroll
    for (int i = 0; i < 2; i++)
        #pragma unroll
        for (int j = 0; j < 8; j++)
            #pragma unroll
            for (int q = 0; q < 4; q++) oacc[i][j][q] = 0.f;
    float rsum[4];
    #pragma unroll
    for (int q = 0; q < 4; q++) rsum[q] = 0.f;

    // prologue: G0 = {Q, K0, V0}; G1 = {K1, V1}
    loadT(Qs,  qkv + (size_t)qbase * 3072 + h * 64);
    loadT(Kb0, qkv + (size_t)kvbase * 3072 + 1024 + h * 64);
    loadT(Vb0, qkv + (size_t)kvbase * 3072 + 2048 + h * 64);
    cp_commit();
    loadT(Kb1, qkv + (size_t)(kvbase + 128) * 3072 + 1024 + h * 64);
    loadT(Vb1, qkv + (size_t)(kvbase + 128) * 3072 + 2048 + h * 64);
    cp_commit();
    cp_wait1();                          // G0 done (Q, K0, V0)
    __syncthreads();

    for (int ch = 0; ch < NCHUNKS; ch++) {
        const uint32_t uK = smem_u32((ch & 1) ? Kb1 : Kb0);
        const uint32_t uV = smem_u32((ch & 1) ? Vb1 : Vb0);

        // ---- two passes of 32 S-cols; exp in regs; PV immediately ----
        #pragma unroll
        for (int p = 0; p < 2; p++) {
            float sacc[2][4][4];
            #pragma unroll
            for (int il = 0; il < 2; il++)
                #pragma unroll
                for (int j = 0; j < 4; j++)
                    #pragma unroll
                    for (int q = 0; q < 4; q++) sacc[il][j][q] = 0.f;

            // S = Q K^T over this 32-col slice (k = 64)
            #pragma unroll
            for (int ks = 0; ks < 4; ks++) {
                const int k0 = ks * 16;
                uint32_t qa[2][4], kb[4][2];
                #pragma unroll
                for (int il = 0; il < 2; il++)
                    ldsm4(qa[il][0], qa[il][1], qa[il][2], qa[il][3],
                          uQ + (((wm * 32 + il * 16 + lm16) * QSTR) + k0 + lh * 8) * 2);
                #pragma unroll
                for (int jj = 0; jj < 2; jj++) {
                    const int c0 = wn * 64 + p * 32 + jj * 16;
                    ldsm4(kb[jj*2][0], kb[jj*2][1], kb[jj*2+1][0], kb[jj*2+1][1],
                          uK + (((c0 + (grp >> 1) * 8 + l8) * KSTR) + k0 + (grp & 1) * 8) * 2);
                }
                #pragma unroll
                for (int il = 0; il < 2; il++)
                    #pragma unroll
                    for (int j = 0; j < 4; j++)
                        mma_f16(sacc[il][j], qa[il], kb[j]);
            }

            // exp + pack to PV A-fragments (register identity) + PV
            #pragma unroll
            for (int j2 = 0; j2 < 2; j2++) {           // two k16 steps per pass
                uint32_t ph[2][4];
                #pragma unroll
                for (int il = 0; il < 2; il++) {
                    float e00 = ex2(sacc[il][2*j2+0][0] * LOG2E_SCALE);
                    float e01 = ex2(sacc[il][2*j2+0][1] * LOG2E_SCALE);
                    float e02 = ex2(sacc[il][2*j2+0][2] * LOG2E_SCALE);
                    float e03 = ex2(sacc[il][2*j2+0][3] * LOG2E_SCALE);
                    float e10 = ex2(sacc[il][2*j2+1][0] * LOG2E_SCALE);
                    float e11 = ex2(sacc[il][2*j2+1][1] * LOG2E_SCALE);
                    float e12 = ex2(sacc[il][2*j2+1][2] * LOG2E_SCALE);
                    float e13 = ex2(sacc[il][2*j2+1][3] * LOG2E_SCALE);
                    rsum[il*2+0] += (e00 + e01) + (e10 + e11);
                    rsum[il*2+1] += (e02 + e03) + (e12 + e13);
                    half2 p0 = __floats2half2_rn(e00, e01);
                    half2 p1 = __floats2half2_rn(e02, e03);
                    half2 p2 = __floats2half2_rn(e10, e11);
                    half2 p3 = __floats2half2_rn(e12, e13);
                    ph[il][0] = *(uint32_t*)&p0;
                    ph[il][1] = *(uint32_t*)&p1;
                    ph[il][2] = *(uint32_t*)&p2;
                    ph[il][3] = *(uint32_t*)&p3;
                }
                const int krow = wn * 64 + p * 32 + j2 * 16;
                uint32_t vb[8][2];
                #pragma unroll
                for (int jj = 0; jj < 4; jj++)
                    ldsm4t(vb[jj*2][0], vb[jj*2][1], vb[jj*2+1][0], vb[jj*2+1][1],
                           uV + (((krow + (grp & 1) * 8 + l8) * VSTR) + jj * 16 + (grp >> 1) * 8) * 2);
                #pragma unroll
                for (int il = 0; il < 2; il++)
                    #pragma unroll
                    for (int j = 0; j < 8; j++)
                        mma_f16(oacc[il][j], ph[il], vb[j]);
            }
        }

        cp_wait0();              // group ch+1 complete (this thread's share)
        __syncthreads();         // all shares complete & visible; buf ch free
        if (ch + 2 < NCHUNKS) {
            loadT((ch & 1) ? Kb1 : Kb0,
                  qkv + (size_t)(kvbase + (ch + 2) * 128) * 3072 + 1024 + h * 64);
            loadT((ch & 1) ? Vb1 : Vb0,
                  qkv + (size_t)(kvbase + (ch + 2) * 128) * 3072 + 2048 + h * 64);
        }
        cp_commit();
    }

    // ---- epilogue: all compute done (last chunk's barrier passed) ----
    // row sums: quad shuffle, then across the 2 wn groups via red
    #pragma unroll
    for (int q = 0; q < 4; q++) {
        rsum[q] += __shfl_xor_sync(0xffffffffu, rsum[q], 1);
        rsum[q] += __shfl_xor_sync(0xffffffffu, rsum[q], 2);
    }
    if (t4 == 0) {
        #pragma unroll
        for (int il = 0; il < 2; il++)
            #pragma unroll
            for (int half = 0; half < 2; half++)
                red[wn * 128 + wm * 32 + il * 16 + g + half * 8] = rsum[il * 2 + half];
    }
    // wn==1 warps: store O partials to fbuf (aliases Q/K smem, now dead)
    if (wn == 1) {
        #pragma unroll
        for (int il = 0; il < 2; il++)
            #pragma unroll
            for (int half = 0; half < 2; half++) {
                const int rl = wm * 32 + il * 16 + g + half * 8;
                #pragma unroll
                for (int j = 0; j < 8; j++)
                    *(float2*)(fbuf + rl * 66 + j * 8 + 2 * t4) =
                        make_float2(oacc[il][j][half * 2 + 0],
                                    oacc[il][j][half * 2 + 1]);
            }
    }
    __syncthreads();
    if (tid < 128)
        linv[tid] = 1.0f / (red[tid] + red[128 + tid]);
    __syncthreads();

    // wn==0 warps: add partner partial, normalize, store fp16
    if (wn == 0) {
        #pragma unroll
        for (int il = 0; il < 2; il++) {
            #pragma unroll
            for (int half = 0; half < 2; half++) {
                const int rr = wm * 32 + il * 16 + g + half * 8;
                const float f = linv[rr];
                __half* orow = oatt + (size_t)(qbase + rr) * Cv + h * 64;
                #pragma unroll
                for (int j = 0; j < 8; j++) {
                    const float2 pv = *(const float2*)(fbuf + rr * 66 + j * 8 + 2 * t4);
                    float v0 = oacc[il][j][half * 2 + 0] + pv.x;
                    float v1 = oacc[il][j][half * 2 + 1] + pv.y;
                    *(half2*)(orow + j * 8 + 2 * t4) = __floats2half2_rn(v0 * f, v1 * f);
                }
            }
        }
    }
}

// ---------------------------------------------------------------------------
// fp16 mma GEMM (R10/R12 version, unchanged): 3-stage cp.async, ldmatrix,
// B natural [k][n]. BM=128, BN=128, BK=64. 256 threads = 8 warps (2m x 4n).
// 2 CTAs/SM. EPI: 1 fp16, 2 +bias+fp32 residual -> fp32, 3 +bias+GELU -> fp16
// ---------------------------------------------------------------------------
template<int EPI>
__global__ void __launch_bounds__(256, 2)
gemm_h(const __half* __restrict__ A, const __half* __restrict__ B,
       void* __restrict__ Cp,
       int K, int lda, int ldb, int ldc,
       const float* __restrict__ bias, const float* __restrict__ res, int ldres)
{
    constexpr int BM = 128, BK = 64, NSTG = 3;
    constexpr int ASTR = 72;
    constexpr int BSTR = 136;

    extern __shared__ __half sh[];
    __half* As = sh;
    __half* Bs = sh + NSTG * BM * ASTR;

    const int tid  = threadIdx.x;
    const int lane = tid & 31, warp = tid >> 5;
    const int wm = warp & 1, wn = warp >> 1;
    const int g = lane >> 2, t4 = lane & 3;
    const int l8 = lane & 7, grp = lane >> 3;
    const int lm16 = lane & 15, lh = lane >> 4;

    const int m0 = blockIdx.y * BM;
    const int n0 = blockIdx.x * 128;
    const int ktiles = K / BK;

    float acc[4][4][4];
    #pragma unroll
    for (int i = 0; i < 4; i++)
        #pragma unroll
        for (int j = 0; j < 4; j++)
            #pragma unroll
            for (int q = 0; q < 4; q++) acc[i][j][q] = 0.f;

    auto loadA = [&](int stg, int kt) {
        __half* as = As + stg * BM * ASTR;
        #pragma unroll
        for (int p = 0; p < 4; p++) {
            int idx = tid + p * 256;
            int row = idx >> 3, c8 = (idx & 7) << 3;
            cp_async16(as + row * ASTR + c8,
                       A + (size_t)(m0 + row) * lda + kt * BK + c8);
        }
    };
    auto loadB = [&](int stg, int kt) {
        __half* bs = Bs + stg * BK * BSTR;
        #pragma unroll
        for (int p = 0; p < 4; p++) {
            int idx = tid + p * 256;
            int row = idx >> 4, c8 = (idx & 15) << 3;
            cp_async16(bs + row * BSTR + c8,
                       B + (size_t)(kt * BK + row) * ldb + n0 + c8);
        }
    };
    auto compute = [&](int stg) {
        const uint32_t uA = smem_u32(As + stg * BM * ASTR);
        const uint32_t uB = smem_u32(Bs + stg * BK * BSTR);
        #pragma unroll
        for (int ks = 0; ks < 4; ks++) {
            const int k0 = ks * 16;
            uint32_t a[4][4], bb[4][2];
            #pragma unroll
            for (int i = 0; i < 4; i++) {
                const int r = wm * 64 + i * 16;
                ldsm4(a[i][0], a[i][1], a[i][2], a[i][3],
                      uA + (((r + lm16) * ASTR) + k0 + lh * 8) * 2);
            }
            #pragma unroll
            for (int jj = 0; jj < 2; jj++) {
                const int c0 = wn * 32 + jj * 16;
                ldsm4t(bb[jj*2][0], bb[jj*2][1], bb[jj*2+1][0], bb[jj*2+1][1],
                       uB + (((k0 + (grp & 1) * 8 + l8) * BSTR) + c0 + (grp >> 1) * 8) * 2);
            }
            #pragma unroll
            for (int i = 0; i < 4; i++)
                #pragma unroll
                for (int j = 0; j < 4; j++)
                    mma_f16(acc[i][j], a[i], bb[j]);
        }
    };

    loadA(0, 0); loadB(0, 0); cp_commit();
    loadA(1, 1); loadB(1, 1); cp_commit();

    int stg = 0;
    for (int kt = 0; kt < ktiles; kt++) {
        cp_wait1();
        __syncthreads();
        const int nxt = kt + 2;
        if (nxt < ktiles) {
            const int ns = (stg + 2 >= NSTG) ? stg + 2 - NSTG : stg + 2;
            loadA(ns, nxt); loadB(ns, nxt);
        }
        cp_commit();
        compute(stg);
        if (++stg == NSTG) stg = 0;
    }

    // epilogue
    #pragma unroll
    for (int i = 0; i < 4; i++) {
        const int r = m0 + wm * 64 + i * 16 + g;
        #pragma unroll
        for (int j = 0; j < 4; j++) {
            const int c = n0 + wn * 32 + j * 8 + 2 * t4;
            #pragma unroll
            for (int half = 0; half < 2; half++) {
                const int rr = r + half * 8;
                float v0 = acc[i][j][half * 2 + 0];
                float v1 = acc[i][j][half * 2 + 1];
                if (EPI == 1) {
                    *(half2*)((__half*)Cp + (size_t)rr * ldc + c) =
                        __floats2half2_rn(v0, v1);
                } else if (EPI == 2) {
                    v0 += bias[c]     + res[(size_t)rr * ldres + c];
                    v1 += bias[c + 1] + res[(size_t)rr * ldres + c + 1];
                    *(float2*)((float*)Cp + (size_t)rr * ldc + c) = make_float2(v0, v1);
                } else {
                    v0 += bias[c];
                    v1 += bias[c + 1];
                    v0 = 0.5f * v0 * (1.0f + erff(v0 * 0.70710678118654752f));
                    v1 = 0.5f * v1 * (1.0f + erff(v1 * 0.70710678118654752f));
                    *(half2*)((__half*)Cp + (size_t)rr * ldc + c) =
                        __floats2half2_rn(v0, v1);
                }
            }
        }
    }
}

// ---------------------------------------------------------------------------
extern "C" void kernel_launch(void* const* d_in, const int* in_sizes, int n_in,
                              void* d_out, int out_size)
{
    const float* x      = (const float*)d_in[0];
    const float* ln1_g  = (const float*)d_in[1];
    const float* ln1_b  = (const float*)d_in[2];
    const float* w_qkv  = (const float*)d_in[3];
    const float* w_proj = (const float*)d_in[4];
    const float* b_proj = (const float*)d_in[5];
    const float* ln2_g  = (const float*)d_in[6];
    const float* ln2_b  = (const float*)d_in[7];
    const float* w_fc1  = (const float*)d_in[8];
    const float* b_fc1  = (const float*)d_in[9];
    const float* w_fc2  = (const float*)d_in[10];
    const float* b_fc2  = (const float*)d_in[11];
    float* out = (float*)d_out;

    float* scratch = nullptr;
    cudaGetSymbolAddress((void**)&scratch, g_scratch);

    float*  x1    = scratch + OFF_X1;
    __half* hbase = (__half*)(scratch + OFF_HBASE);
    __half* xn    = hbase + HOFF_XN;
    __half* qkv   = hbase + HOFF_QKV;
    __half* oatt  = hbase + HOFF_OATT;
    __half* hmid  = hbase + HOFF_HMID;
    __half* wqkvH = hbase + HOFF_WQKV;
    __half* wprojH= hbase + HOFF_WPROJ;
    __half* wfc1H = hbase + HOFF_WFC1;
    __half* wfc2H = hbase + HOFF_WFC2;

    const int smemG   = (3 * 128 * 72 + 3 * 64 * 136) * 2;     // 107520 B
    const int smemAtt = 46080 * 2 + (256 + 128) * 4;           // 93696 B
    cudaFuncSetAttribute(gemm_h<1>, cudaFuncAttributeMaxDynamicSharedMemorySize, smemG);
    cudaFuncSetAttribute(gemm_h<2>, cudaFuncAttributeMaxDynamicSharedMemorySize, smemG);
    cudaFuncSetAttribute(gemm_h<3>, cudaFuncAttributeMaxDynamicSharedMemorySize, smemG);
    cudaFuncSetAttribute(fused_attn, cudaFuncAttributeMaxDynamicSharedMemorySize, smemAtt);

    // 0. convert all weights to fp16
    convert_h<<<12288, 256>>>(w_qkv, wqkvH, w_proj, wprojH, w_fc1, wfc1H, w_fc2, wfc2H);

    // 1. LN1
    ln_kernel<<<Rv, 256>>>(x, ln1_g, ln1_b, xn);

    // 2. qkv = xn @ w_qkv
    gemm_h<1><<<dim3(24, 32), 256, smemG>>>(
        xn, wqkvH, qkv, 1024, 1024, 3072, 3072, nullptr, nullptr, 0);

    // 3. fused attention
    fused_attn<<<dim3(1, 16, 32), 256, smemAtt>>>(qkv, oatt);

    // 4. x1 = x + oatt @ w_proj + b_proj
    gemm_h<2><<<dim3(8, 32), 256, smemG>>>(
        oatt, wprojH, x1, 1024, 1024, 1024, 1024, b_proj, x, 1024);

    // 5. LN2
    ln_kernel<<<Rv, 256>>>(x1, ln2_g, ln2_b, xn);

    // 6. hmid = gelu(xn @ w_fc1 + b_fc1)
    gemm_h<3><<<dim3(32, 32), 256, smemG>>>(
        xn, wfc1H, hmid, 1024, 1024, 4096, 4096, b_fc1, nullptr, 0);

    // 7. out = x1 + hmid @ w_fc2 + b_fc2
    gemm_h<2><<<dim3(8, 32), 256, smemG>>>(
        hmid, wfc2H, out, 4096, 4096, 1024, 1024, b_fc2, x1, 1024);
}

// round 15
// speedup vs baseline: 1.0415x; 1.0415x over previous
#include <cuda_runtime.h>
#include <cuda_fp16.h>
#include <math.h>
#include <stdint.h>

// ---------------------------------------------------------------------------
#define Bv   2
#define Nv   2048
#define Cv   1024
#define Hv   16
#define Dv   64
#define HIDv 4096
#define Rv   (Bv*Nv)

#define OFF_X1        0LL
#define OFF_HBASE     4194304LL
#define SCRATCH_TOTAL 29360128LL

#define HOFF_XN     0LL
#define HOFF_QKV    4194304LL
#define HOFF_OATT   16777216LL
#define HOFF_HMID   20971520LL
#define HOFF_WQKV   37748736LL
#define HOFF_WPROJ  40894464LL
#define HOFF_WFC1   41943040LL
#define HOFF_WFC2   46137344LL

__device__ float g_scratch[SCRATCH_TOTAL];

// ---------------------------------------------------------------------------
__device__ __forceinline__ float ex2(float x) {
    float y;
    asm("ex2.approx.f32 %0, %1;" : "=f"(y) : "f"(x));
    return y;
}
__device__ __forceinline__ uint32_t smem_u32(const void* p) {
    uint32_t a;
    asm("{ .reg .u64 t; cvta.to.shared.u64 t, %1; cvt.u32.u64 %0, t; }"
        : "=r"(a) : "l"(p));
    return a;
}
__device__ __forceinline__ void cp_async16(void* sm, const void* gm) {
    uint32_t s = smem_u32(sm);
    asm volatile("cp.async.cg.shared.global [%0], [%1], 16;" :: "r"(s), "l"(gm));
}
__device__ __forceinline__ void cp_commit() {
    asm volatile("cp.async.commit_group;");
}
__device__ __forceinline__ void cp_wait0() {
    asm volatile("cp.async.wait_group 0;");
}
__device__ __forceinline__ void cp_wait1() {
    asm volatile("cp.async.wait_group 1;");
}
__device__ __forceinline__ void mma_f16(float* d, const uint32_t* a, const uint32_t* b) {
    asm volatile(
        "mma.sync.aligned.m16n8k16.row.col.f32.f16.f16.f32 "
        "{%0,%1,%2,%3}, {%4,%5,%6,%7}, {%8,%9}, {%0,%1,%2,%3};"
        : "+f"(d[0]), "+f"(d[1]), "+f"(d[2]), "+f"(d[3])
        : "r"(a[0]), "r"(a[1]), "r"(a[2]), "r"(a[3]), "r"(b[0]), "r"(b[1]));
}
__device__ __forceinline__ void ldsm4(uint32_t& r0, uint32_t& r1, uint32_t& r2,
                                      uint32_t& r3, uint32_t a) {
    asm volatile("ldmatrix.sync.aligned.m8n8.x4.shared.b16 {%0,%1,%2,%3}, [%4];"
        : "=r"(r0), "=r"(r1), "=r"(r2), "=r"(r3) : "r"(a));
}
__device__ __forceinline__ void ldsm4t(uint32_t& r0, uint32_t& r1, uint32_t& r2,
                                       uint32_t& r3, uint32_t a) {
    asm volatile("ldmatrix.sync.aligned.m8n8.x4.trans.shared.b16 {%0,%1,%2,%3}, [%4];"
        : "=r"(r0), "=r"(r1), "=r"(r2), "=r"(r3) : "r"(a));
}

// ---------------------------------------------------------------------------
// LayerNorm: fp32 in, fp16 out. 256 threads/row, single float4 pass.
// ---------------------------------------------------------------------------
__global__ void ln_kernel(const float* __restrict__ x,
                          const float* __restrict__ g,
                          const float* __restrict__ b,
                          __half* __restrict__ out)
{
    const int row = blockIdx.x;
    const int tid = threadIdx.x;
    const float4 v = *((const float4*)(x + (size_t)row * Cv) + tid);

    float lsum = v.x + v.y + v.z + v.w;
    float lsq  = v.x * v.x + v.y * v.y + v.z * v.z + v.w * v.w;

    __shared__ float s1[8], s2[8], sm_[2];
    for (int o = 16; o; o >>= 1) {
        lsum += __shfl_down_sync(0xffffffffu, lsum, o);
        lsq  += __shfl_down_sync(0xffffffffu, lsq,  o);
    }
    const int wid = tid >> 5, lid = tid & 31;
    if (!lid) { s1[wid] = lsum; s2[wid] = lsq; }
    __syncthreads();
    if (tid < 8) {
        float a = s1[tid], c = s2[tid];
        for (int o = 4; o; o >>= 1) {
            a += __shfl_down_sync(0xffu, a, o);
            c += __shfl_down_sync(0xffu, c, o);
        }
        if (!tid) {
            const float mean = a * (1.0f / Cv);
            sm_[0] = mean;
            sm_[1] = rsqrtf(c * (1.0f / Cv) - mean * mean + 1e-5f);
        }
    }
    __syncthreads();
    const float mean = sm_[0], rstd = sm_[1];

    const float4 gg = *((const float4*)g + tid);
    const float4 bb = *((const float4*)b + tid);
    half2 o0 = __floats2half2_rn((v.x - mean) * rstd * gg.x + bb.x,
                                 (v.y - mean) * rstd * gg.y + bb.y);
    half2 o1 = __floats2half2_rn((v.z - mean) * rstd * gg.z + bb.z,
                                 (v.w - mean) * rstd * gg.w + bb.w);
    uint2 st = make_uint2(*(uint32_t*)&o0, *(uint32_t*)&o1);
    *((uint2*)(out + (size_t)row * Cv) + tid) = st;
}

// ---------------------------------------------------------------------------
// One streaming fp32 -> fp16 convert over all 4 weight matrices
// ---------------------------------------------------------------------------
__global__ void convert_h(const float* __restrict__ wqkv,  __half* __restrict__ oqkv,
                          const float* __restrict__ wproj, __half* __restrict__ oproj,
                          const float* __restrict__ wfc1,  __half* __restrict__ ofc1,
                          const float* __restrict__ wfc2,  __half* __restrict__ ofc2)
{
    long long i = (long long)blockIdx.x * blockDim.x + threadIdx.x;
    const float* src; __half* dst;
    if (i < 786432)        { src = wqkv;  dst = oqkv; }
    else if (i < 1048576)  { src = wproj; dst = oproj; i -= 786432; }
    else if (i < 2097152)  { src = wfc1;  dst = ofc1;  i -= 1048576; }
    else                   { src = wfc2;  dst = ofc2;  i -= 2097152; }
    float4 v = *(const float4*)(src + i * 4);
    *(half2*)(dst + i * 4)     = __floats2half2_rn(v.x, v.y);
    *(half2*)(dst + i * 4 + 2) = __floats2half2_rn(v.z, v.w);
}

// ---------------------------------------------------------------------------
// Fused flash attention (R13 version), warps 4m x 2n, Q fragments cached.
// Q columns of qkv are pre-scaled by 0.125*log2(e) in the qkv GEMM epilogue,
// so exp is a bare ex2().
// Grid (1,16,32), 256 threads = 8 warps, 2 CTAs/SM.
// ---------------------------------------------------------------------------
#define QSTR 72
#define KSTR 72
#define VSTR 72
#define PSTR 136
#define NCHUNKS 16

__global__ void __launch_bounds__(256, 2)
fused_attn(const __half* __restrict__ qkv, __half* __restrict__ oatt)
{
    extern __shared__ __half sh[];
    __half* Qs  = sh;                            // 128*72
    __half* Kb0 = sh + 9216;                     // 128*72
    __half* Kb1 = sh + 18432;                    // 128*72
    __half* Vs  = sh + 27648;                    // 128*72
    __half* Ps  = sh + 36864;                    // 128*136
    float*  red  = (float*)(sh + 54272);         // 256 floats
    float*  linv = red + 256;                    // 128 floats

    const int tid  = threadIdx.x;
    const int lane = tid & 31, warp = tid >> 5;
    const int wm = warp & 3, wn = warp >> 2;     // 4m x 2n
    const int g = lane >> 2, t4 = lane & 3;
    const int l8 = lane & 7, grp = lane >> 3;
    const int lm16 = lane & 15, lh = lane >> 4;

    const uint32_t uQ = smem_u32(Qs), uV = smem_u32(Vs), uP = smem_u32(Ps);

    const int bh = blockIdx.z;
    const int b = bh >> 4, h = bh & 15;
    const int qbase = b * Nv + blockIdx.y * 128;
    const int kvbase = b * Nv;

    auto loadT = [&](__half* dst, const __half* src) {
        #pragma unroll
        for (int p = 0; p < 4; p++) {
            int idx = tid + p * 256;
            int row = idx >> 3, c8 = (idx & 7) << 3;
            cp_async16(dst + row * QSTR + c8, src + (size_t)row * 3072 + c8);
        }
    };

    float oacc[2][4][4];
    #pragma unroll
    for (int i = 0; i < 2; i++)
        #pragma unroll
        for (int j = 0; j < 4; j++)
            #pragma unroll
            for (int q = 0; q < 4; q++) oacc[i][j][q] = 0.f;
    float rsum[4];
    #pragma unroll
    for (int q = 0; q < 4; q++) rsum[q] = 0.f;

    // prologue: G0 = {Q, K0, V0}; G1 = {K1}
    loadT(Qs,  qkv + (size_t)qbase * 3072 + h * 64);
    loadT(Kb0, qkv + (size_t)kvbase * 3072 + 1024 + h * 64);
    loadT(Vs,  qkv + (size_t)kvbase * 3072 + 2048 + h * 64);
    cp_commit();
    loadT(Kb1, qkv + (size_t)(kvbase + 128) * 3072 + 1024 + h * 64);
    cp_commit();
    cp_wait1();
    __syncthreads();

    // ---- cache Q fragments: rows wm*32..+32, full k=64 -> qa[2][4][4] ----
    uint32_t qa[2][4][4];
    #pragma unroll
    for (int il = 0; il < 2; il++)
        #pragma unroll
        for (int ks = 0; ks < 4; ks++)
            ldsm4(qa[il][ks][0], qa[il][ks][1], qa[il][ks][2], qa[il][ks][3],
                  uQ + (((wm * 32 + il * 16 + lm16) * QSTR) + ks * 16 + lh * 8) * 2);

    for (int ch = 0; ch < NCHUNKS; ch++) {
        const uint32_t uK = smem_u32((ch & 1) ? Kb1 : Kb0);

        // ---- S = Q K^T (two n-passes of 32 cols); exp; store P(half) ----
        #pragma unroll
        for (int p = 0; p < 2; p++) {
            float sacc[2][4][4];
            #pragma unroll
            for (int il = 0; il < 2; il++)
                #pragma unroll
                for (int j = 0; j < 4; j++)
                    #pragma unroll
                    for (int q = 0; q < 4; q++) sacc[il][j][q] = 0.f;

            #pragma unroll
            for (int ks = 0; ks < 4; ks++) {
                const int k0 = ks * 16;
                uint32_t bb[4][2];
                #pragma unroll
                for (int jj = 0; jj < 2; jj++) {
                    const int c0 = wn * 64 + p * 32 + jj * 16;
                    ldsm4(bb[jj*2][0], bb[jj*2][1], bb[jj*2+1][0], bb[jj*2+1][1],
                          uK + (((c0 + (grp >> 1) * 8 + l8) * KSTR) + k0 + (grp & 1) * 8) * 2);
                }
                #pragma unroll
                for (int il = 0; il < 2; il++)
                    #pragma unroll
                    for (int j = 0; j < 4; j++)
                        mma_f16(sacc[il][j], qa[il][ks], bb[j]);
            }

            #pragma unroll
            for (int il = 0; il < 2; il++) {
                const int r = wm * 32 + il * 16 + g;
                #pragma unroll
                for (int j = 0; j < 4; j++) {
                    const int c = wn * 64 + p * 32 + j * 8 + 2 * t4;
                    #pragma unroll
                    for (int half = 0; half < 2; half++) {
                        float v0 = ex2(sacc[il][j][half * 2 + 0]);
                        float v1 = ex2(sacc[il][j][half * 2 + 1]);
                        rsum[il * 2 + half] += v0 + v1;
                        *(half2*)(Ps + (r + half * 8) * PSTR + c) =
                            __floats2half2_rn(v0, v1);
                    }
                }
            }
        }

        cp_wait0();              // V(ch) and K(ch+1) arrived
        __syncthreads();         // P + V + K(ch+1) visible; K(ch) buffer free

        if (ch + 2 < NCHUNKS)
            loadT((ch & 1) ? Kb1 : Kb0,
                  qkv + (size_t)(kvbase + (ch + 2) * 128) * 3072 + 1024 + h * 64);
        cp_commit();

        // ---- O += P @ V : warp tile 32 rows x 32 cols, full k=128 ----
        #pragma unroll
        for (int ks = 0; ks < 8; ks++) {
            const int k0 = ks * 16;
            uint32_t a[2][4], bb[4][2];
            #pragma unroll
            for (int i = 0; i < 2; i++) {
                const int r = wm * 32 + i * 16;
                ldsm4(a[i][0], a[i][1], a[i][2], a[i][3],
                      uP + (((r + lm16) * PSTR) + k0 + lh * 8) * 2);
            }
            #pragma unroll
            for (int jj = 0; jj < 2; jj++) {
                const int c0 = wn * 32 + jj * 16;
                ldsm4t(bb[jj*2][0], bb[jj*2][1], bb[jj*2+1][0], bb[jj*2+1][1],
                       uV + (((k0 + (grp & 1) * 8 + l8) * VSTR) + c0 + (grp >> 1) * 8) * 2);
            }
            #pragma unroll
            for (int i = 0; i < 2; i++)
                #pragma unroll
                for (int j = 0; j < 4; j++)
                    mma_f16(oacc[i][j], a[i], bb[j]);
        }

        __syncthreads();         // Vs & Ps free; K(ch+1) visible for next S
        if (ch + 1 < NCHUNKS)
            loadT(Vs, qkv + (size_t)(kvbase + (ch + 1) * 128) * 3072 + 2048 + h * 64);
        cp_commit();
    }

    // ---- row-sum reduction: quad shuffle, then across the 2 wn groups ----
    #pragma unroll
    for (int q = 0; q < 4; q++) {
        rsum[q] += __shfl_xor_sync(0xffffffffu, rsum[q], 1);
        rsum[q] += __shfl_xor_sync(0xffffffffu, rsum[q], 2);
    }
    if (t4 == 0) {
        #pragma unroll
        for (int il = 0; il < 2; il++)
            #pragma unroll
            for (int half = 0; half < 2; half++)
                red[wn * 128 + wm * 32 + il * 16 + g + half * 8] = rsum[il * 2 + half];
    }
    __syncthreads();
    if (tid < 128)
        linv[tid] = 1.0f / (red[tid] + red[128 + tid]);
    __syncthreads();

    // ---- epilogue: O * (1/l) -> fp16 store (complete tiling, no reduce) ----
    #pragma unroll
    for (int i = 0; i < 2; i++) {
        #pragma unroll
        for (int half = 0; half < 2; half++) {
            const int rr = wm * 32 + i * 16 + g + half * 8;
            const float f = linv[rr];
            __half* orow = oatt + (size_t)(qbase + rr) * Cv + h * 64;
            #pragma unroll
            for (int j = 0; j < 4; j++) {
                const int c = wn * 32 + j * 8 + 2 * t4;
                *(half2*)(orow + c) =
                    __floats2half2_rn(oacc[i][j][half * 2 + 0] * f,
                                      oacc[i][j][half * 2 + 1] * f);
            }
        }
    }
}

// ---------------------------------------------------------------------------
// fp16 mma GEMM (R10/R12 version): 3-stage cp.async, ldmatrix, B natural
// [k][n]. BM=128, BN=128, BK=64. 256 threads = 8 warps (2m x 4n). 2 CTAs/SM.
// EPI: 1 fp16, 2 +bias+fp32 residual -> fp32, 3 +bias+GELU -> fp16,
//      4 fp16 with Q columns (c < 1024) pre-scaled by 0.125*log2(e)
// ---------------------------------------------------------------------------
template<int EPI>
__global__ void __launch_bounds__(256, 2)
gemm_h(const __half* __restrict__ A, const __half* __restrict__ B,
       void* __restrict__ Cp,
       int K, int lda, int ldb, int ldc,
       const float* __restrict__ bias, const float* __restrict__ res, int ldres)
{
    constexpr int BM = 128, BK = 64, NSTG = 3;
    constexpr int ASTR = 72;
    constexpr int BSTR = 136;

    extern __shared__ __half sh[];
    __half* As = sh;
    __half* Bs = sh + NSTG * BM * ASTR;

    const int tid  = threadIdx.x;
    const int lane = tid & 31, warp = tid >> 5;
    const int wm = warp & 1, wn = warp >> 1;
    const int g = lane >> 2, t4 = lane & 3;
    const int l8 = lane & 7, grp = lane >> 3;
    const int lm16 = lane & 15, lh = lane >> 4;

    const int m0 = blockIdx.y * BM;
    const int n0 = blockIdx.x * 128;
    const int ktiles = K / BK;

    float acc[4][4][4];
    #pragma unroll
    for (int i = 0; i < 4; i++)
        #pragma unroll
        for (int j = 0; j < 4; j++)
            #pragma unroll
            for (int q = 0; q < 4; q++) acc[i][j][q] = 0.f;

    auto loadA = [&](int stg, int kt) {
        __half* as = As + stg * BM * ASTR;
        #pragma unroll
        for (int p = 0; p < 4; p++) {
            int idx = tid + p * 256;
            int row = idx >> 3, c8 = (idx & 7) << 3;
            cp_async16(as + row * ASTR + c8,
                       A + (size_t)(m0 + row) * lda + kt * BK + c8);
        }
    };
    auto loadB = [&](int stg, int kt) {
        __half* bs = Bs + stg * BK * BSTR;
        #pragma unroll
        for (int p = 0; p < 4; p++) {
            int idx = tid + p * 256;
            int row = idx >> 4, c8 = (idx & 15) << 3;
            cp_async16(bs + row * BSTR + c8,
                       B + (size_t)(kt * BK + row) * ldb + n0 + c8);
        }
    };
    auto compute = [&](int stg) {
        const uint32_t uA = smem_u32(As + stg * BM * ASTR);
        const uint32_t uB = smem_u32(Bs + stg * BK * BSTR);
        #pragma unroll
        for (int ks = 0; ks < 4; ks++) {
            const int k0 = ks * 16;
            uint32_t a[4][4], bb[4][2];
            #pragma unroll
            for (int i = 0; i < 4; i++) {
                const int r = wm * 64 + i * 16;
                ldsm4(a[i][0], a[i][1], a[i][2], a[i][3],
                      uA + (((r + lm16) * ASTR) + k0 + lh * 8) * 2);
            }
            #pragma unroll
            for (int jj = 0; jj < 2; jj++) {
                const int c0 = wn * 32 + jj * 16;
                ldsm4t(bb[jj*2][0], bb[jj*2][1], bb[jj*2+1][0], bb[jj*2+1][1],
                       uB + (((k0 + (grp & 1) * 8 + l8) * BSTR) + c0 + (grp >> 1) * 8) * 2);
            }
            #pragma unroll
            for (int i = 0; i < 4; i++)
                #pragma unroll
                for (int j = 0; j < 4; j++)
                    mma_f16(acc[i][j], a[i], bb[j]);
        }
    };

    loadA(0, 0); loadB(0, 0); cp_commit();
    loadA(1, 1); loadB(1, 1); cp_commit();

    int stg = 0;
    for (int kt = 0; kt < ktiles; kt++) {
        cp_wait1();
        __syncthreads();
        const int nxt = kt + 2;
        if (nxt < ktiles) {
            const int ns = (stg + 2 >= NSTG) ? stg + 2 - NSTG : stg + 2;
            loadA(ns, nxt); loadB(ns, nxt);
        }
        cp_commit();
        compute(stg);
        if (++stg == NSTG) stg = 0;
    }

    // epilogue
    #pragma unroll
    for (int i = 0; i < 4; i++) {
        const int r = m0 + wm * 64 + i * 16 + g;
        #pragma unroll
        for (int j = 0; j < 4; j++) {
            const int c = n0 + wn * 32 + j * 8 + 2 * t4;
            #pragma unroll
            for (int half = 0; half < 2; half++) {
                const int rr = r + half * 8;
                float v0 = acc[i][j][half * 2 + 0];
                float v1 = acc[i][j][half * 2 + 1];
                if (EPI == 1) {
                    *(half2*)((__half*)Cp + (size_t)rr * ldc + c) =
                        __floats2half2_rn(v0, v1);
                } else if (EPI == 4) {
                    // qkv output: Q columns pre-scaled by 0.125*log2(e)
                    const float s = (c < 1024) ? 0.18033688011112042f : 1.0f;
                    *(half2*)((__half*)Cp + (size_t)rr * ldc + c) =
                        __floats2half2_rn(v0 * s, v1 * s);
                } else if (EPI == 2) {
                    v0 += bias[c]     + res[(size_t)rr * ldres + c];
                    v1 += bias[c + 1] + res[(size_t)rr * ldres + c + 1];
                    *(float2*)((float*)Cp + (size_t)rr * ldc + c) = make_float2(v0, v1);
                } else {
                    v0 += bias[c];
                    v1 += bias[c + 1];
                    v0 = 0.5f * v0 * (1.0f + erff(v0 * 0.70710678118654752f));
                    v1 = 0.5f * v1 * (1.0f + erff(v1 * 0.70710678118654752f));
                    *(half2*)((__half*)Cp + (size_t)rr * ldc + c) =
                        __floats2half2_rn(v0, v1);
                }
            }
        }
    }
}

// ---------------------------------------------------------------------------
extern "C" void kernel_launch(void* const* d_in, const int* in_sizes, int n_in,
                              void* d_out, int out_size)
{
    const float* x      = (const float*)d_in[0];
    const float* ln1_g  = (const float*)d_in[1];
    const float* ln1_b  = (const float*)d_in[2];
    const float* w_qkv  = (const float*)d_in[3];
    const float* w_proj = (const float*)d_in[4];
    const float* b_proj = (const float*)d_in[5];
    const float* ln2_g  = (const float*)d_in[6];
    const float* ln2_b  = (const float*)d_in[7];
    const float* w_fc1  = (const float*)d_in[8];
    const float* b_fc1  = (const float*)d_in[9];
    const float* w_fc2  = (const float*)d_in[10];
    const float* b_fc2  = (const float*)d_in[11];
    float* out = (float*)d_out;

    float* scratch = nullptr;
    cudaGetSymbolAddress((void**)&scratch, g_scratch);

    float*  x1    = scratch + OFF_X1;
    __half* hbase = (__half*)(scratch + OFF_HBASE);
    __half* xn    = hbase + HOFF_XN;
    __half* qkv   = hbase + HOFF_QKV;
    __half* oatt  = hbase + HOFF_OATT;
    __half* hmid  = hbase + HOFF_HMID;
    __half* wqkvH = hbase + HOFF_WQKV;
    __half* wprojH= hbase + HOFF_WPROJ;
    __half* wfc1H = hbase + HOFF_WFC1;
    __half* wfc2H = hbase + HOFF_WFC2;

    const int smemG   = (3 * 128 * 72 + 3 * 64 * 136) * 2;     // 107520 B
    const int smemAtt = 54272 * 2 + (256 + 128) * 4;           // 110080 B
    cudaFuncSetAttribute(gemm_h<4>, cudaFuncAttributeMaxDynamicSharedMemorySize, smemG);
    cudaFuncSetAttribute(gemm_h<2>, cudaFuncAttributeMaxDynamicSharedMemorySize, smemG);
    cudaFuncSetAttribute(gemm_h<3>, cudaFuncAttributeMaxDynamicSharedMemorySize, smemG);
    cudaFuncSetAttribute(fused_attn, cudaFuncAttributeMaxDynamicSharedMemorySize, smemAtt);

    // 0. convert all weights to fp16
    convert_h<<<12288, 256>>>(w_qkv, wqkvH, w_proj, wprojH, w_fc1, wfc1H, w_fc2, wfc2H);

    // 1. LN1
    ln_kernel<<<Rv, 256>>>(x, ln1_g, ln1_b, xn);

    // 2. qkv = xn @ w_qkv   (Q columns pre-scaled for softmax)
    gemm_h<4><<<dim3(24, 32), 256, smemG>>>(
        xn, wqkvH, qkv, 1024, 1024, 3072, 3072, nullptr, nullptr, 0);

    // 3. fused attention
    fused_attn<<<dim3(1, 16, 32), 256, smemAtt>>>(qkv, oatt);

    // 4. x1 = x + oatt @ w_proj + b_proj
    gemm_h<2><<<dim3(8, 32), 256, smemG>>>(
        oatt, wprojH, x1, 1024, 1024, 1024, 1024, b_proj, x, 1024);

    // 5. LN2
    ln_kernel<<<Rv, 256>>>(x1, ln2_g, ln2_b, xn);

    // 6. hmid = gelu(xn @ w_fc1 + b_fc1)
    gemm_h<3><<<dim3(32, 32), 256, smemG>>>(
        xn, wfc1H, hmid, 1024, 1024, 4096, 4096, b_fc1, nullptr, 0);

    // 7. out = x1 + hmid @ w_fc2 + b_fc2
    gemm_h<2><<<dim3(8, 32), 256, smemG>>>(
        hmid, wfc2H, out, 4096, 4096, 1024, 1024, b_fc2, x1, 1024);
}

// round 16
// speedup vs baseline: 1.0416x; 1.0001x over previous
#include <cuda_runtime.h>
#include <cuda_fp16.h>
#include <math.h>
#include <stdint.h>

// ---------------------------------------------------------------------------
#define Bv   2
#define Nv   2048
#define Cv   1024
#define Hv   16
#define Dv   64
#define HIDv 4096
#define Rv   (Bv*Nv)

#define OFF_X1        0LL
#define OFF_HBASE     4194304LL
#define SCRATCH_TOTAL 29360128LL

#define HOFF_XN     0LL
#define HOFF_QKV    4194304LL
#define HOFF_OATT   16777216LL
#define HOFF_HMID   20971520LL
#define HOFF_WQKV   37748736LL
#define HOFF_WPROJ  40894464LL
#define HOFF_WFC1   41943040LL
#define HOFF_WFC2   46137344LL

__device__ float g_scratch[SCRATCH_TOTAL];

// ---------------------------------------------------------------------------
__device__ __forceinline__ float ex2(float x) {
    float y;
    asm("ex2.approx.f32 %0, %1;" : "=f"(y) : "f"(x));
    return y;
}
__device__ __forceinline__ uint32_t smem_u32(const void* p) {
    uint32_t a;
    asm("{ .reg .u64 t; cvta.to.shared.u64 t, %1; cvt.u32.u64 %0, t; }"
        : "=r"(a) : "l"(p));
    return a;
}
__device__ __forceinline__ void cp_async16(void* sm, const void* gm) {
    uint32_t s = smem_u32(sm);
    asm volatile("cp.async.cg.shared.global [%0], [%1], 16;" :: "r"(s), "l"(gm));
}
__device__ __forceinline__ void cp_commit() {
    asm volatile("cp.async.commit_group;");
}
__device__ __forceinline__ void cp_wait0() {
    asm volatile("cp.async.wait_group 0;");
}
__device__ __forceinline__ void cp_wait1() {
    asm volatile("cp.async.wait_group 1;");
}
__device__ __forceinline__ void mma_f16(float* d, const uint32_t* a, const uint32_t* b) {
    asm volatile(
        "mma.sync.aligned.m16n8k16.row.col.f32.f16.f16.f32 "
        "{%0,%1,%2,%3}, {%4,%5,%6,%7}, {%8,%9}, {%0,%1,%2,%3};"
        : "+f"(d[0]), "+f"(d[1]), "+f"(d[2]), "+f"(d[3])
        : "r"(a[0]), "r"(a[1]), "r"(a[2]), "r"(a[3]), "r"(b[0]), "r"(b[1]));
}
__device__ __forceinline__ void ldsm4(uint32_t& r0, uint32_t& r1, uint32_t& r2,
                                      uint32_t& r3, uint32_t a) {
    asm volatile("ldmatrix.sync.aligned.m8n8.x4.shared.b16 {%0,%1,%2,%3}, [%4];"
        : "=r"(r0), "=r"(r1), "=r"(r2), "=r"(r3) : "r"(a));
}
__device__ __forceinline__ void ldsm4t(uint32_t& r0, uint32_t& r1, uint32_t& r2,
                                       uint32_t& r3, uint32_t a) {
    asm volatile("ldmatrix.sync.aligned.m8n8.x4.trans.shared.b16 {%0,%1,%2,%3}, [%4];"
        : "=r"(r0), "=r"(r1), "=r"(r2), "=r"(r3) : "r"(a));
}

// ---------------------------------------------------------------------------
// LN body (one row, 256 threads, single float4 pass): fp32 in, fp16 out
// ---------------------------------------------------------------------------
__device__ __forceinline__ void ln_row(const float* __restrict__ x,
                                       const float* __restrict__ g,
                                       const float* __restrict__ b,
                                       __half* __restrict__ out, int row)
{
    const int tid = threadIdx.x;
    const float4 v = *((const float4*)(x + (size_t)row * Cv) + tid);

    float lsum = v.x + v.y + v.z + v.w;
    float lsq  = v.x * v.x + v.y * v.y + v.z * v.z + v.w * v.w;

    __shared__ float s1[8], s2[8], sm_[2];
    for (int o = 16; o; o >>= 1) {
        lsum += __shfl_down_sync(0xffffffffu, lsum, o);
        lsq  += __shfl_down_sync(0xffffffffu, lsq,  o);
    }
    const int wid = tid >> 5, lid = tid & 31;
    if (!lid) { s1[wid] = lsum; s2[wid] = lsq; }
    __syncthreads();
    if (tid < 8) {
        float a = s1[tid], c = s2[tid];
        for (int o = 4; o; o >>= 1) {
            a += __shfl_down_sync(0xffu, a, o);
            c += __shfl_down_sync(0xffu, c, o);
        }
        if (!tid) {
            const float mean = a * (1.0f / Cv);
            sm_[0] = mean;
            sm_[1] = rsqrtf(c * (1.0f / Cv) - mean * mean + 1e-5f);
        }
    }
    __syncthreads();
    const float mean = sm_[0], rstd = sm_[1];

    const float4 gg = *((const float4*)g + tid);
    const float4 bb = *((const float4*)b + tid);
    half2 o0 = __floats2half2_rn((v.x - mean) * rstd * gg.x + bb.x,
                                 (v.y - mean) * rstd * gg.y + bb.y);
    half2 o1 = __floats2half2_rn((v.z - mean) * rstd * gg.z + bb.z,
                                 (v.w - mean) * rstd * gg.w + bb.w);
    uint2 st = make_uint2(*(uint32_t*)&o0, *(uint32_t*)&o1);
    *((uint2*)(out + (size_t)row * Cv) + tid) = st;
}

__global__ void ln_kernel(const float* __restrict__ x,
                          const float* __restrict__ g,
                          const float* __restrict__ b,
                          __half* __restrict__ out)
{
    ln_row(x, g, b, out, blockIdx.x);
}

// ---------------------------------------------------------------------------
// Fused init: blocks [0,4096) do LN1; blocks [4096,16384) convert the four
// weight matrices fp32 -> fp16 (float4 granularity).
// ---------------------------------------------------------------------------
__global__ void init_fused(const float* __restrict__ x,
                           const float* __restrict__ ln1_g,
                           const float* __restrict__ ln1_b,
                           __half* __restrict__ xn,
                           const float* __restrict__ wqkv,  __half* __restrict__ oqkv,
                           const float* __restrict__ wproj, __half* __restrict__ oproj,
                           const float* __restrict__ wfc1,  __half* __restrict__ ofc1,
                           const float* __restrict__ wfc2,  __half* __restrict__ ofc2)
{
    if (blockIdx.x < 4096) {
        ln_row(x, ln1_g, ln1_b, xn, blockIdx.x);
        return;
    }
    long long i = (long long)(blockIdx.x - 4096) * blockDim.x + threadIdx.x;
    const float* src; __half* dst;
    if (i < 786432)        { src = wqkv;  dst = oqkv; }
    else if (i < 1048576)  { src = wproj; dst = oproj; i -= 786432; }
    else if (i < 2097152)  { src = wfc1;  dst = ofc1;  i -= 1048576; }
    else                   { src = wfc2;  dst = ofc2;  i -= 2097152; }
    float4 v = *(const float4*)(src + i * 4);
    *(half2*)(dst + i * 4)     = __floats2half2_rn(v.x, v.y);
    *(half2*)(dst + i * 4 + 2) = __floats2half2_rn(v.z, v.w);
}

// ---------------------------------------------------------------------------
// Fused flash attention (R13/R15 version), warps 4m x 2n, Q fragments cached.
// Q columns of qkv are pre-scaled by 0.125*log2(e) in the qkv GEMM epilogue.
// Grid (1,16,32), 256 threads = 8 warps, 2 CTAs/SM.
// ---------------------------------------------------------------------------
#define QSTR 72
#define KSTR 72
#define VSTR 72
#define PSTR 136
#define NCHUNKS 16

__global__ void __launch_bounds__(256, 2)
fused_attn(const __half* __restrict__ qkv, __half* __restrict__ oatt)
{
    extern __shared__ __half sh[];
    __half* Qs  = sh;                            // 128*72
    __half* Kb0 = sh + 9216;                     // 128*72
    __half* Kb1 = sh + 18432;                    // 128*72
    __half* Vs  = sh + 27648;                    // 128*72
    __half* Ps  = sh + 36864;                    // 128*136
    float*  red  = (float*)(sh + 54272);         // 256 floats
    float*  linv = red + 256;                    // 128 floats

    const int tid  = threadIdx.x;
    const int lane = tid & 31, warp = tid >> 5;
    const int wm = warp & 3, wn = warp >> 2;     // 4m x 2n
    const int g = lane >> 2, t4 = lane & 3;
    const int l8 = lane & 7, grp = lane >> 3;
    const int lm16 = lane & 15, lh = lane >> 4;

    const uint32_t uQ = smem_u32(Qs), uV = smem_u32(Vs), uP = smem_u32(Ps);

    const int bh = blockIdx.z;
    const int b = bh >> 4, h = bh & 15;
    const int qbase = b * Nv + blockIdx.y * 128;
    const int kvbase = b * Nv;

    auto loadT = [&](__half* dst, const __half* src) {
        #pragma unroll
        for (int p = 0; p < 4; p++) {
            int idx = tid + p * 256;
            int row = idx >> 3, c8 = (idx & 7) << 3;
            cp_async16(dst + row * QSTR + c8, src + (size_t)row * 3072 + c8);
        }
    };

    float oacc[2][4][4];
    #pragma unroll
    for (int i = 0; i < 2; i++)
        #pragma unroll
        for (int j = 0; j < 4; j++)
            #pragma unroll
            for (int q = 0; q < 4; q++) oacc[i][j][q] = 0.f;
    float rsum[4];
    #pragma unroll
    for (int q = 0; q < 4; q++) rsum[q] = 0.f;

    // prologue: G0 = {Q, K0, V0}; G1 = {K1}
    loadT(Qs,  qkv + (size_t)qbase * 3072 + h * 64);
    loadT(Kb0, qkv + (size_t)kvbase * 3072 + 1024 + h * 64);
    loadT(Vs,  qkv + (size_t)kvbase * 3072 + 2048 + h * 64);
    cp_commit();
    loadT(Kb1, qkv + (size_t)(kvbase + 128) * 3072 + 1024 + h * 64);
    cp_commit();
    cp_wait1();
    __syncthreads();

    // ---- cache Q fragments: rows wm*32..+32, full k=64 -> qa[2][4][4] ----
    uint32_t qa[2][4][4];
    #pragma unroll
    for (int il = 0; il < 2; il++)
        #pragma unroll
        for (int ks = 0; ks < 4; ks++)
            ldsm4(qa[il][ks][0], qa[il][ks][1], qa[il][ks][2], qa[il][ks][3],
                  uQ + (((wm * 32 + il * 16 + lm16) * QSTR) + ks * 16 + lh * 8) * 2);

    for (int ch = 0; ch < NCHUNKS; ch++) {
        const uint32_t uK = smem_u32((ch & 1) ? Kb1 : Kb0);

        // ---- S = Q K^T (two n-passes of 32 cols); exp; store P(half) ----
        #pragma unroll
        for (int p = 0; p < 2; p++) {
            float sacc[2][4][4];
            #pragma unroll
            for (int il = 0; il < 2; il++)
                #pragma unroll
                for (int j = 0; j < 4; j++)
                    #pragma unroll
                    for (int q = 0; q < 4; q++) sacc[il][j][q] = 0.f;

            #pragma unroll
            for (int ks = 0; ks < 4; ks++) {
                const int k0 = ks * 16;
                uint32_t bb[4][2];
                #pragma unroll
                for (int jj = 0; jj < 2; jj++) {
                    const int c0 = wn * 64 + p * 32 + jj * 16;
                    ldsm4(bb[jj*2][0], bb[jj*2][1], bb[jj*2+1][0], bb[jj*2+1][1],
                          uK + (((c0 + (grp >> 1) * 8 + l8) * KSTR) + k0 + (grp & 1) * 8) * 2);
                }
                #pragma unroll
                for (int il = 0; il < 2; il++)
                    #pragma unroll
                    for (int j = 0; j < 4; j++)
                        mma_f16(sacc[il][j], qa[il][ks], bb[j]);
            }

            #pragma unroll
            for (int il = 0; il < 2; il++) {
                const int r = wm * 32 + il * 16 + g;
                #pragma unroll
                for (int j = 0; j < 4; j++) {
                    const int c = wn * 64 + p * 32 + j * 8 + 2 * t4;
                    #pragma unroll
                    for (int half = 0; half < 2; half++) {
                        float v0 = ex2(sacc[il][j][half * 2 + 0]);
                        float v1 = ex2(sacc[il][j][half * 2 + 1]);
                        rsum[il * 2 + half] += v0 + v1;
                        *(half2*)(Ps + (r + half * 8) * PSTR + c) =
                            __floats2half2_rn(v0, v1);
                    }
                }
            }
        }

        cp_wait0();              // V(ch) and K(ch+1) arrived
        __syncthreads();         // P + V + K(ch+1) visible; K(ch) buffer free

        if (ch + 2 < NCHUNKS)
            loadT((ch & 1) ? Kb1 : Kb0,
                  qkv + (size_t)(kvbase + (ch + 2) * 128) * 3072 + 1024 + h * 64);
        cp_commit();

        // ---- O += P @ V : warp tile 32 rows x 32 cols, full k=128 ----
        #pragma unroll
        for (int ks = 0; ks < 8; ks++) {
            const int k0 = ks * 16;
            uint32_t a[2][4], bb[4][2];
            #pragma unroll
            for (int i = 0; i < 2; i++) {
                const int r = wm * 32 + i * 16;
                ldsm4(a[i][0], a[i][1], a[i][2], a[i][3],
                      uP + (((r + lm16) * PSTR) + k0 + lh * 8) * 2);
            }
            #pragma unroll
            for (int jj = 0; jj < 2; jj++) {
                const int c0 = wn * 32 + jj * 16;
                ldsm4t(bb[jj*2][0], bb[jj*2][1], bb[jj*2+1][0], bb[jj*2+1][1],
                       uV + (((k0 + (grp & 1) * 8 + l8) * VSTR) + c0 + (grp >> 1) * 8) * 2);
            }
            #pragma unroll
            for (int i = 0; i < 2; i++)
                #pragma unroll
                for (int j = 0; j < 4; j++)
                    mma_f16(oacc[i][j], a[i], bb[j]);
        }

        __syncthreads();         // Vs & Ps free; K(ch+1) visible for next S
        if (ch + 1 < NCHUNKS)
            loadT(Vs, qkv + (size_t)(kvbase + (ch + 1) * 128) * 3072 + 2048 + h * 64);
        cp_commit();
    }

    // ---- row-sum reduction: quad shuffle, then across the 2 wn groups ----
    #pragma unroll
    for (int q = 0; q < 4; q++) {
        rsum[q] += __shfl_xor_sync(0xffffffffu, rsum[q], 1);
        rsum[q] += __shfl_xor_sync(0xffffffffu, rsum[q], 2);
    }
    if (t4 == 0) {
        #pragma unroll
        for (int il = 0; il < 2; il++)
            #pragma unroll
            for (int half = 0; half < 2; half++)
                red[wn * 128 + wm * 32 + il * 16 + g + half * 8] = rsum[il * 2 + half];
    }
    __syncthreads();
    if (tid < 128)
        linv[tid] = 1.0f / (red[tid] + red[128 + tid]);
    __syncthreads();

    // ---- epilogue: O * (1/l) -> fp16 store (complete tiling, no reduce) ----
    #pragma unroll
    for (int i = 0; i < 2; i++) {
        #pragma unroll
        for (int half = 0; half < 2; half++) {
            const int rr = wm * 32 + i * 16 + g + half * 8;
            const float f = linv[rr];
            __half* orow = oatt + (size_t)(qbase + rr) * Cv + h * 64;
            #pragma unroll
            for (int j = 0; j < 4; j++) {
                const int c = wn * 32 + j * 8 + 2 * t4;
                *(half2*)(orow + c) =
                    __floats2half2_rn(oacc[i][j][half * 2 + 0] * f,
                                      oacc[i][j][half * 2 + 1] * f);
            }
        }
    }
}

// ---------------------------------------------------------------------------
// fp16 mma GEMM: 3-stage cp.async, ldmatrix, B natural [k][n].
// BM=128, BN=128, BK=64. 256 threads = 8 warps (2m x 4n). 2 CTAs/SM.
// EPI: 1 fp16, 2 +bias+fp32 residual -> fp32, 3 +bias+GELU -> fp16,
//      4 fp16 with Q columns (c < 1024) pre-scaled by 0.125*log2(e)
// ---------------------------------------------------------------------------
template<int EPI>
__global__ void __launch_bounds__(256, 2)
gemm_h(const __half* __restrict__ A, const __half* __restrict__ B,
       void* __restrict__ Cp,
       int K, int lda, int ldb, int ldc,
       const float* __restrict__ bias, const float* __restrict__ res, int ldres)
{
    constexpr int BM = 128, BK = 64, NSTG = 3;
    constexpr int ASTR = 72;
    constexpr int BSTR = 136;

    extern __shared__ __half sh[];
    __half* As = sh;
    __half* Bs = sh + NSTG * BM * ASTR;

    const int tid  = threadIdx.x;
    const int lane = tid & 31, warp = tid >> 5;
    const int wm = warp & 1, wn = warp >> 1;
    const int g = lane >> 2, t4 = lane & 3;
    const int l8 = lane & 7, grp = lane >> 3;
    const int lm16 = lane & 15, lh = lane >> 4;

    const int m0 = blockIdx.y * BM;
    const int n0 = blockIdx.x * 128;
    const int ktiles = K / BK;

    float acc[4][4][4];
    #pragma unroll
    for (int i = 0; i < 4; i++)
        #pragma unroll
        for (int j = 0; j < 4; j++)
            #pragma unroll
            for (int q = 0; q < 4; q++) acc[i][j][q] = 0.f;

    auto loadA = [&](int stg, int kt) {
        __half* as = As + stg * BM * ASTR;
        #pragma unroll
        for (int p = 0; p < 4; p++) {
            int idx = tid + p * 256;
            int row = idx >> 3, c8 = (idx & 7) << 3;
            cp_async16(as + row * ASTR + c8,
                       A + (size_t)(m0 + row) * lda + kt * BK + c8);
        }
    };
    auto loadB = [&](int stg, int kt) {
        __half* bs = Bs + stg * BK * BSTR;
        #pragma unroll
        for (int p = 0; p < 4; p++) {
            int idx = tid + p * 256;
            int row = idx >> 4, c8 = (idx & 15) << 3;
            cp_async16(bs + row * BSTR + c8,
                       B + (size_t)(kt * BK + row) * ldb + n0 + c8);
        }
    };
    auto compute = [&](int stg) {
        const uint32_t uA = smem_u32(As + stg * BM * ASTR);
        const uint32_t uB = smem_u32(Bs + stg * BK * BSTR);
        #pragma unroll
        for (int ks = 0; ks < 4; ks++) {
            const int k0 = ks * 16;
            uint32_t a[4][4], bb[4][2];
            #pragma unroll
            for (int i = 0; i < 4; i++) {
                const int r = wm * 64 + i * 16;
                ldsm4(a[i][0], a[i][1], a[i][2], a[i][3],
                      uA + (((r + lm16) * ASTR) + k0 + lh * 8) * 2);
            }
            #pragma unroll
            for (int jj = 0; jj < 2; jj++) {
                const int c0 = wn * 32 + jj * 16;
                ldsm4t(bb[jj*2][0], bb[jj*2][1], bb[jj*2+1][0], bb[jj*2+1][1],
                       uB + (((k0 + (grp & 1) * 8 + l8) * BSTR) + c0 + (grp >> 1) * 8) * 2);
            }
            #pragma unroll
            for (int i = 0; i < 4; i++)
                #pragma unroll
                for (int j = 0; j < 4; j++)
                    mma_f16(acc[i][j], a[i], bb[j]);
        }
    };

    loadA(0, 0); loadB(0, 0); cp_commit();
    loadA(1, 1); loadB(1, 1); cp_commit();

    int stg = 0;
    for (int kt = 0; kt < ktiles; kt++) {
        cp_wait1();
        __syncthreads();
        const int nxt = kt + 2;
        if (nxt < ktiles) {
            const int ns = (stg + 2 >= NSTG) ? stg + 2 - NSTG : stg + 2;
            loadA(ns, nxt); loadB(ns, nxt);
        }
        cp_commit();
        compute(stg);
        if (++stg == NSTG) stg = 0;
    }

    // epilogue
    #pragma unroll
    for (int i = 0; i < 4; i++) {
        const int r = m0 + wm * 64 + i * 16 + g;
        #pragma unroll
        for (int j = 0; j < 4; j++) {
            const int c = n0 + wn * 32 + j * 8 + 2 * t4;
            #pragma unroll
            for (int half = 0; half < 2; half++) {
                const int rr = r + half * 8;
                float v0 = acc[i][j][half * 2 + 0];
                float v1 = acc[i][j][half * 2 + 1];
                if (EPI == 1) {
                    *(half2*)((__half*)Cp + (size_t)rr * ldc + c) =
                        __floats2half2_rn(v0, v1);
                } else if (EPI == 4) {
                    const float s = (c < 1024) ? 0.18033688011112042f : 1.0f;
                    *(half2*)((__half*)Cp + (size_t)rr * ldc + c) =
                        __floats2half2_rn(v0 * s, v1 * s);
                } else if (EPI == 2) {
                    v0 += bias[c]     + res[(size_t)rr * ldres + c];
                    v1 += bias[c + 1] + res[(size_t)rr * ldres + c + 1];
                    *(float2*)((float*)Cp + (size_t)rr * ldc + c) = make_float2(v0, v1);
                } else {
                    v0 += bias[c];
                    v1 += bias[c + 1];
                    v0 = 0.5f * v0 * (1.0f + erff(v0 * 0.70710678118654752f));
                    v1 = 0.5f * v1 * (1.0f + erff(v1 * 0.70710678118654752f));
                    *(half2*)((__half*)Cp + (size_t)rr * ldc + c) =
                        __floats2half2_rn(v0, v1);
                }
            }
        }
    }
}

// ---------------------------------------------------------------------------
extern "C" void kernel_launch(void* const* d_in, const int* in_sizes, int n_in,
                              void* d_out, int out_size)
{
    const float* x      = (const float*)d_in[0];
    const float* ln1_g  = (const float*)d_in[1];
    const float* ln1_b  = (const float*)d_in[2];
    const float* w_qkv  = (const float*)d_in[3];
    const float* w_proj = (const float*)d_in[4];
    const float* b_proj = (const float*)d_in[5];
    const float* ln2_g  = (const float*)d_in[6];
    const float* ln2_b  = (const float*)d_in[7];
    const float* w_fc1  = (const float*)d_in[8];
    const float* b_fc1  = (const float*)d_in[9];
    const float* w_fc2  = (const float*)d_in[10];
    const float* b_fc2  = (const float*)d_in[11];
    float* out = (float*)d_out;

    float* scratch = nullptr;
    cudaGetSymbolAddress((void**)&scratch, g_scratch);

    float*  x1    = scratch + OFF_X1;
    __half* hbase = (__half*)(scratch + OFF_HBASE);
    __half* xn    = hbase + HOFF_XN;
    __half* qkv   = hbase + HOFF_QKV;
    __half* oatt  = hbase + HOFF_OATT;
    __half* hmid  = hbase + HOFF_HMID;
    __half* wqkvH = hbase + HOFF_WQKV;
    __half* wprojH= hbase + HOFF_WPROJ;
    __half* wfc1H = hbase + HOFF_WFC1;
    __half* wfc2H = hbase + HOFF_WFC2;

    const int smemG   = (3 * 128 * 72 + 3 * 64 * 136) * 2;     // 107520 B
    const int smemAtt = 54272 * 2 + (256 + 128) * 4;           // 110080 B
    cudaFuncSetAttribute(gemm_h<4>, cudaFuncAttributeMaxDynamicSharedMemorySize, smemG);
    cudaFuncSetAttribute(gemm_h<2>, cudaFuncAttributeMaxDynamicSharedMemorySize, smemG);
    cudaFuncSetAttribute(gemm_h<3>, cudaFuncAttributeMaxDynamicSharedMemorySize, smemG);
    cudaFuncSetAttribute(fused_attn, cudaFuncAttributeMaxDynamicSharedMemorySize, smemAtt);

    // 0. fused: LN1 (blocks 0..4095) + weight fp16 convert (blocks 4096..16383)
    init_fused<<<16384, 256>>>(x, ln1_g, ln1_b, xn,
                               w_qkv, wqkvH, w_proj, wprojH,
                               w_fc1, wfc1H, w_fc2, wfc2H);

    // 1. qkv = xn @ w_qkv   (Q columns pre-scaled for softmax)
    gemm_h<4><<<dim3(24, 32), 256, smemG>>>(
        xn, wqkvH, qkv, 1024, 1024, 3072, 3072, nullptr, nullptr, 0);

    // 2. fused attention
    fused_attn<<<dim3(1, 16, 32), 256, smemAtt>>>(qkv, oatt);

    // 3. x1 = x + oatt @ w_proj + b_proj
    gemm_h<2><<<dim3(8, 32), 256, smemG>>>(
        oatt, wprojH, x1, 1024, 1024, 1024, 1024, b_proj, x, 1024);

    // 4. LN2
    ln_kernel<<<Rv, 256>>>(x1, ln2_g, ln2_b, xn);

    // 5. hmid = gelu(xn @ w_fc1 + b_fc1)
    gemm_h<3><<<dim3(32, 32), 256, smemG>>>(
        xn, wfc1H, hmid, 1024, 1024, 4096, 4096, b_fc1, nullptr, 0);

    // 6. out = x1 + hmid @ w_fc2 + b_fc2
    gemm_h<2><<<dim3(8, 32), 256, smemG>>>(
        hmid, wfc2H, out, 4096, 4096, 1024, 1024, b_fc2, x1, 1024);
}